// round 6
// baseline (speedup 1.0000x reference)
#include <cuda_runtime.h>
#include <stdint.h>

#define N_NODES 50000
#define N_EDGES 800000
#define FEAT    128

// Scratch (static device globals; no allocation allowed)
__device__ float g_sums1[(size_t)N_NODES * FEAT];
__device__ float g_sums2[(size_t)N_NODES * FEAT];
__device__ float g_h[(size_t)N_NODES * FEAT];
__device__ float g_cnt[N_NODES];
__device__ int   g_idx_is32;

// ---------------------------------------------------------------------------
// Detect edge_index dtype: reference declares int64 but JAX (x64 off) emits
// int32. Read the first 64 entries as int64 — if any is outside [0, N_NODES),
// the buffer is really int32. Deterministic, runs every replay.
// ---------------------------------------------------------------------------
__global__ void detect_kernel(const long long* __restrict__ ei) {
    if (threadIdx.x == 0 && blockIdx.x == 0) {
        int is32 = 0;
        for (int i = 0; i < 64; i++) {
            long long v = ei[i];
            if (v < 0 || v >= N_NODES) { is32 = 1; break; }
        }
        g_idx_is32 = is32;
    }
}

// ---------------------------------------------------------------------------
// Zero the accumulators (replay-safe: graph replays re-zero every time)
// ---------------------------------------------------------------------------
__global__ void zero_kernel() {
    const int total4 = (N_NODES * FEAT) / 4;   // 1.6M float4 per array
    int tid = blockIdx.x * blockDim.x + threadIdx.x;
    int stride = gridDim.x * blockDim.x;
    float4 z = make_float4(0.f, 0.f, 0.f, 0.f);
    for (int i = tid; i < total4; i += stride) {
        ((float4*)g_sums1)[i] = z;
        ((float4*)g_sums2)[i] = z;
    }
    for (int i = tid; i < N_NODES; i += stride) g_cnt[i] = 0.f;
}

// ---------------------------------------------------------------------------
// Edge scatter: one warp per edge. Lane l handles floats [4l, 4l+4).
// Coalesced 512B row gather + vectorized L2 reduction (red.v4).
// Index dtype selected at runtime via g_idx_is32 (uniform branch).
// ---------------------------------------------------------------------------
__global__ void scatter_kernel(const float* __restrict__ src_feat,
                               const void* __restrict__ ei,
                               float* __restrict__ sums,
                               float* __restrict__ cnt) {
    int gw   = (blockIdx.x * blockDim.x + threadIdx.x) >> 5;
    int lane = threadIdx.x & 31;
    if (gw >= N_EDGES) return;

    int s, d;
    if (g_idx_is32) {
        const int* e32 = (const int*)ei;
        s = __ldg(&e32[gw]);
        d = __ldg(&e32[N_EDGES + gw]);
    } else {
        const long long* e64 = (const long long*)ei;
        s = (int)__ldg(&e64[gw]);
        d = (int)__ldg(&e64[N_EDGES + gw]);
    }

    const float4* sp = (const float4*)(src_feat + (int64_t)s * FEAT);
    float4 v = __ldg(&sp[lane]);

    float* dp = sums + (int64_t)d * FEAT + lane * 4;
    asm volatile("red.global.add.v4.f32 [%0], {%1, %2, %3, %4};"
                 :: "l"(dp), "f"(v.x), "f"(v.y), "f"(v.z), "f"(v.w)
                 : "memory");

    if (cnt != nullptr && lane == 0)
        atomicAdd(cnt + d, 1.0f);
}

// ---------------------------------------------------------------------------
// Fused SAGE layer: out[n][j] = act( (sums[n]/max(cnt,1)) . Wl[:,j]
//                                    + xroot[n] . Wr[:,j] + b[j] )
// Persistent blocks, both weight matrices staged in shared once per block.
// JP = padded J (multiple of 4, divides 256 thread mapping), JREAL = true J.
// Block = 256 threads: thread t -> quad jq = t % (JP/4), node-group mg = t/(JP/4).
// ---------------------------------------------------------------------------
template <int JP, int JREAL, bool RELU>
__global__ void __launch_bounds__(256, 1)
layer_kernel(const float* __restrict__ sums, const float* __restrict__ cnt,
             const float* __restrict__ xroot,
             const float* __restrict__ Wl, const float* __restrict__ Wr,
             const float* __restrict__ bias, float* __restrict__ out) {
    constexpr int K   = 128;
    constexpr int TM  = 16;            // nodes per tile
    constexpr int NQ  = JP / 4;        // float4 quads across J
    constexpr int NMG = 256 / NQ;      // node-groups
    constexpr int NPT = TM / NMG;      // nodes per thread

    extern __shared__ float smem[];
    float* sWl  = smem;                 // K*JP
    float* sWr  = sWl + K * JP;         // K*JP
    float* sb   = sWr + K * JP;         // JP
    float* sA   = sb + JP;              // TM*K (aggregated/mean)
    float* sX   = sA + TM * K;          // TM*K (root)
    float* sinv = sX + TM * K;          // TM

    const int t = threadIdx.x;

    // Stage weights (zero-padded to JP columns)
    for (int idx = t; idx < K * JP; idx += 256) {
        int k = idx / JP, j = idx % JP;
        float wl = 0.f, wr = 0.f;
        if (j < JREAL) {
            wl = __ldg(&Wl[k * JREAL + j]);
            wr = __ldg(&Wr[k * JREAL + j]);
        }
        sWl[idx] = wl;
        sWr[idx] = wr;
    }
    for (int idx = t; idx < JP; idx += 256)
        sb[idx] = (idx < JREAL) ? __ldg(&bias[idx]) : 0.f;

    const int jq = t % NQ;
    const int mg = t / NQ;
    const int ntiles = N_NODES / TM;   // 50000/16 = 3125 exactly

    for (int tile = blockIdx.x; tile < ntiles; tile += gridDim.x) {
        const int base = tile * TM;

        __syncthreads();   // previous tile's compute done before reloading sA/sX
        if (t < TM) {
            float c = __ldg(&cnt[base + t]);
            sinv[t] = 1.0f / fmaxf(c, 1.0f);
        }
        __syncthreads();

        // Stage node tile: mean-aggregated features and root features
        for (int idx = t; idx < TM * (K / 4); idx += 256) {
            int m = idx / (K / 4), q = idx % (K / 4);
            const float4* spq = (const float4*)(sums  + (int64_t)(base + m) * K);
            const float4* xpq = (const float4*)(xroot + (int64_t)(base + m) * K);
            float4 sv = __ldg(&spq[q]);
            float inv = sinv[m];
            sv.x *= inv; sv.y *= inv; sv.z *= inv; sv.w *= inv;
            ((float4*)(sA + m * K))[q] = sv;
            ((float4*)(sX + m * K))[q] = __ldg(&xpq[q]);
        }
        __syncthreads();

        float4 acc[NPT];
#pragma unroll
        for (int p = 0; p < NPT; p++) acc[p] = make_float4(0.f, 0.f, 0.f, 0.f);

#pragma unroll 4
        for (int k = 0; k < K; k++) {
            float4 wl = ((const float4*)(sWl + k * JP))[jq];
            float4 wr = ((const float4*)(sWr + k * JP))[jq];
#pragma unroll
            for (int p = 0; p < NPT; p++) {
                int m = mg * NPT + p;
                float a  = sA[m * K + k];   // warp-broadcast
                float xv = sX[m * K + k];   // warp-broadcast
                acc[p].x += a * wl.x + xv * wr.x;
                acc[p].y += a * wl.y + xv * wr.y;
                acc[p].z += a * wl.z + xv * wr.z;
                acc[p].w += a * wl.w + xv * wr.w;
            }
        }

        if (jq * 4 < JREAL) {
            float4 bq = ((const float4*)sb)[jq];
#pragma unroll
            for (int p = 0; p < NPT; p++) {
                int m = mg * NPT + p;
                float4 r;
                r.x = acc[p].x + bq.x;
                r.y = acc[p].y + bq.y;
                r.z = acc[p].z + bq.z;
                r.w = acc[p].w + bq.w;
                if (RELU) {
                    r.x = fmaxf(r.x, 0.f);
                    r.y = fmaxf(r.y, 0.f);
                    r.z = fmaxf(r.z, 0.f);
                    r.w = fmaxf(r.w, 0.f);
                }
                *(float4*)(out + (int64_t)(base + m) * JREAL + jq * 4) = r;
            }
        }
    }
}

// ---------------------------------------------------------------------------
extern "C" void kernel_launch(void* const* d_in, const int* in_sizes, int n_in,
                              void* d_out, int out_size) {
    const float*     x   = (const float*)d_in[0];
    const void*      ei  = d_in[1];
    const float*     Wl1 = (const float*)d_in[2];
    const float*     Wr1 = (const float*)d_in[3];
    const float*     b1  = (const float*)d_in[4];
    const float*     Wl2 = (const float*)d_in[5];
    const float*     Wr2 = (const float*)d_in[6];
    const float*     b2  = (const float*)d_in[7];
    float*           out = (float*)d_out;

    float *sums1, *sums2, *hbuf, *cnt;
    cudaGetSymbolAddress((void**)&sums1, g_sums1);
    cudaGetSymbolAddress((void**)&sums2, g_sums2);
    cudaGetSymbolAddress((void**)&hbuf,  g_h);
    cudaGetSymbolAddress((void**)&cnt,   g_cnt);

    // Dynamic shared sizes
    const int SMEM1 = (2 * 128 * 128 + 128 + 2 * 16 * 128 + 16) * 4;  // 148032 B
    const int SMEM2 = (2 * 128 * 64  + 64  + 2 * 16 * 128 + 16) * 4;  //  82240 B
    cudaFuncSetAttribute(layer_kernel<128, 128, true>,
                         cudaFuncAttributeMaxDynamicSharedMemorySize, SMEM1);
    cudaFuncSetAttribute(layer_kernel<64, 40, false>,
                         cudaFuncAttributeMaxDynamicSharedMemorySize, SMEM2);

    // 0. detect index dtype (int32 vs int64)
    detect_kernel<<<1, 32>>>((const long long*)ei);

    // 1. zero accumulators + counts
    zero_kernel<<<2048, 256>>>();

    // 2. aggregate layer-1 neighbors (+ degree counts, computed once)
    scatter_kernel<<<(N_EDGES * 32) / 256, 256>>>(x, ei, sums1, cnt);

    // 3. h = relu(mean_agg @ Wl1 + x @ Wr1 + b1)
    layer_kernel<128, 128, true><<<152, 256, SMEM1>>>(sums1, cnt, x, Wl1, Wr1, b1, hbuf);

    // 4. aggregate layer-2 neighbors (counts reused)
    scatter_kernel<<<(N_EDGES * 32) / 256, 256>>>(hbuf, ei, sums2, nullptr);

    // 5. out = mean_agg2 @ Wl2 + h @ Wr2 + b2
    layer_kernel<64, 40, false><<<304, 256, SMEM2>>>(sums2, cnt, hbuf, Wl2, Wr2, b2, out);
}

// round 8
// speedup vs baseline: 1.0478x; 1.0478x over previous
#include <cuda_runtime.h>
#include <stdint.h>

#define N_NODES 50000
#define N_EDGES 800000
#define FEAT    128

// Scratch (static device globals; no allocation allowed)
__device__ float g_sums1[(size_t)N_NODES * FEAT];
__device__ float g_sums2[(size_t)N_NODES * FEAT];
__device__ float g_h[(size_t)N_NODES * FEAT];
__device__ float g_cnt[N_NODES];
__device__ int   g_idx_is32;

// ---------------------------------------------------------------------------
// Detect edge_index dtype: reference declares int64 but JAX (x64 off) emits
// int32. Read the first 64 entries as int64 — if any is outside [0, N_NODES),
// the buffer is really int32. Deterministic, runs every replay.
// ---------------------------------------------------------------------------
__global__ void detect_kernel(const long long* __restrict__ ei) {
    if (threadIdx.x == 0 && blockIdx.x == 0) {
        int is32 = 0;
        for (int i = 0; i < 64; i++) {
            long long v = ei[i];
            if (v < 0 || v >= N_NODES) { is32 = 1; break; }
        }
        g_idx_is32 = is32;
    }
}

// ---------------------------------------------------------------------------
// Zero the accumulators (replay-safe: graph replays re-zero every time)
// ---------------------------------------------------------------------------
__global__ void zero_kernel() {
    const int total4 = (N_NODES * FEAT) / 4;
    int tid = blockIdx.x * blockDim.x + threadIdx.x;
    int stride = gridDim.x * blockDim.x;
    float4 z = make_float4(0.f, 0.f, 0.f, 0.f);
    for (int i = tid; i < total4; i += stride) {
        ((float4*)g_sums1)[i] = z;
        ((float4*)g_sums2)[i] = z;
    }
    for (int i = tid; i < N_NODES; i += stride) g_cnt[i] = 0.f;
}

// ---------------------------------------------------------------------------
// Edge scatter: one warp per edge. Lane l handles floats [4l, 4l+4).
// Coalesced 512B row gather + vectorized L2 reduction (red.v4).
// ---------------------------------------------------------------------------
__global__ void scatter_kernel(const float* __restrict__ src_feat,
                               const void* __restrict__ ei,
                               float* __restrict__ sums,
                               float* __restrict__ cnt) {
    int gw   = (blockIdx.x * blockDim.x + threadIdx.x) >> 5;
    int lane = threadIdx.x & 31;
    if (gw >= N_EDGES) return;

    int s, d;
    if (g_idx_is32) {
        const int* e32 = (const int*)ei;
        s = __ldg(&e32[gw]);
        d = __ldg(&e32[N_EDGES + gw]);
    } else {
        const long long* e64 = (const long long*)ei;
        s = (int)__ldg(&e64[gw]);
        d = (int)__ldg(&e64[N_EDGES + gw]);
    }

    const float4* sp = (const float4*)(src_feat + (int64_t)s * FEAT);
    float4 v = __ldg(&sp[lane]);

    float* dp = sums + (int64_t)d * FEAT + lane * 4;
    asm volatile("red.global.add.v4.f32 [%0], {%1, %2, %3, %4};"
                 :: "l"(dp), "f"(v.x), "f"(v.y), "f"(v.z), "f"(v.w)
                 : "memory");

    if (cnt != nullptr && lane == 0)
        atomicAdd(cnt + d, 1.0f);
}

// ---------------------------------------------------------------------------
// Fused SAGE layer as ONE register-tiled GEMM over concatenated depth K=256:
//   U[n] = [ sums[n]/max(cnt,1) (128) , xroot[n] (128) ]
//   W    = [ Wl ; Wr ]  (256 x JREAL), bias b
//   out[n][j] = act( U[n] . W[:,j] + b[j] )
//
// Persistent CTAs (1/SM), weights staged once. Per tile:
//   sU staged TRANSPOSED [k][m] -> mainloop does 3x LDS.128 per 32 FMAs.
// Thread tile: 4 nodes x 8 cols (32 accumulators).
//   TM nodes/tile, JP padded cols. NCG=JP/8 col-groups, NNG=256/NCG node-groups,
//   NPT=TM/NNG=4 nodes/thread.
// ---------------------------------------------------------------------------
template <int TM, int JP, int JREAL, bool RELU>
__global__ void __launch_bounds__(256, 1)
layer_kernel(const float* __restrict__ sums, const float* __restrict__ cnt,
             const float* __restrict__ xroot,
             const float* __restrict__ Wl, const float* __restrict__ Wr,
             const float* __restrict__ bias, float* __restrict__ out) {
    constexpr int K   = 256;
    constexpr int KH  = 128;
    constexpr int NCG = JP / 8;
    constexpr int NNG = 256 / NCG;
    constexpr int NPT = TM / NNG;
    static_assert(NPT == 4, "thread tile is 4 nodes x 8 cols");

    extern __shared__ float smem[];
    float* sW = smem;              // K*JP       [k][j]
    float* sU = sW + K * JP;       // K*TM       [k][m] (transposed)
    float* sb = sU + K * TM;       // JP

    const int t = threadIdx.x;

    // Stage concatenated weights (zero-padded cols)
    for (int idx = t; idx < KH * JP; idx += 256) {
        int k = idx / JP, j = idx % JP;
        float wl = 0.f, wr = 0.f;
        if (j < JREAL) {
            wl = __ldg(&Wl[k * JREAL + j]);
            wr = __ldg(&Wr[k * JREAL + j]);
        }
        sW[k * JP + j]        = wl;
        sW[(k + KH) * JP + j] = wr;
    }
    for (int idx = t; idx < JP; idx += 256)
        sb[idx] = (idx < JREAL) ? __ldg(&bias[idx]) : 0.f;

    const int tc = t % NCG;   // col group   -> cols  [tc*8, tc*8+8)
    const int tn = t / NCG;   // node group  -> nodes [tn*4, tn*4+4)
    const int ntiles = (N_NODES + TM - 1) / TM;

    for (int tile = blockIdx.x; tile < ntiles; tile += gridDim.x) {
        const int base = tile * TM;

        __syncthreads();   // previous tile's mainloop done before restaging sU

        // Stage sU transposed. idx -> (k4, m); warp lanes walk m (conflict-free
        // STS, consecutive banks). Gather reads are 16B/lane at 512B stride —
        // L2-resident (both tables << 126MB L2).
        for (int idx = t; idx < (K / 4) * TM; idx += 256) {
            int k4 = idx / TM, m = idx % TM;
            int node = min(base + m, N_NODES - 1);
            float4 v;
            if (k4 < KH / 4) {
                v = __ldg((const float4*)(sums + (int64_t)node * FEAT) + k4);
                float inv = 1.0f / fmaxf(__ldg(&cnt[node]), 1.0f);
                v.x *= inv; v.y *= inv; v.z *= inv; v.w *= inv;
            } else {
                v = __ldg((const float4*)(xroot + (int64_t)node * FEAT) + (k4 - KH / 4));
            }
            int k = k4 * 4;
            sU[(k + 0) * TM + m] = v.x;
            sU[(k + 1) * TM + m] = v.y;
            sU[(k + 2) * TM + m] = v.z;
            sU[(k + 3) * TM + m] = v.w;
        }
        __syncthreads();

        float acc[NPT][8];
#pragma unroll
        for (int p = 0; p < NPT; p++)
#pragma unroll
            for (int j = 0; j < 8; j++) acc[p][j] = 0.f;

#pragma unroll 4
        for (int k = 0; k < K; k++) {
            float4 a  = *(const float4*)(sU + k * TM + tn * 4);
            float4 w0 = *(const float4*)(sW + k * JP + tc * 8);
            float4 w1 = *(const float4*)(sW + k * JP + tc * 8 + 4);
            float av[4] = {a.x, a.y, a.z, a.w};
#pragma unroll
            for (int p = 0; p < NPT; p++) {
                acc[p][0] += av[p] * w0.x;
                acc[p][1] += av[p] * w0.y;
                acc[p][2] += av[p] * w0.z;
                acc[p][3] += av[p] * w0.w;
                acc[p][4] += av[p] * w1.x;
                acc[p][5] += av[p] * w1.y;
                acc[p][6] += av[p] * w1.z;
                acc[p][7] += av[p] * w1.w;
            }
        }

        if (tc * 8 < JREAL) {   // JREAL is a multiple of 8; whole group in or out
            float4 b0 = *(const float4*)(sb + tc * 8);
            float4 b1 = *(const float4*)(sb + tc * 8 + 4);
#pragma unroll
            for (int p = 0; p < NPT; p++) {
                int node = base + tn * 4 + p;
                if (node < N_NODES) {
                    float4 r0, r1;
                    r0.x = acc[p][0] + b0.x;  r0.y = acc[p][1] + b0.y;
                    r0.z = acc[p][2] + b0.z;  r0.w = acc[p][3] + b0.w;
                    r1.x = acc[p][4] + b1.x;  r1.y = acc[p][5] + b1.y;
                    r1.z = acc[p][6] + b1.z;  r1.w = acc[p][7] + b1.w;
                    if (RELU) {
                        r0.x = fmaxf(r0.x, 0.f); r0.y = fmaxf(r0.y, 0.f);
                        r0.z = fmaxf(r0.z, 0.f); r0.w = fmaxf(r0.w, 0.f);
                        r1.x = fmaxf(r1.x, 0.f); r1.y = fmaxf(r1.y, 0.f);
                        r1.z = fmaxf(r1.z, 0.f); r1.w = fmaxf(r1.w, 0.f);
                    }
                    float* op = out + (int64_t)node * JREAL + tc * 8;
                    *(float4*)op       = r0;
                    *(float4*)(op + 4) = r1;
                }
            }
        }
    }
}

// ---------------------------------------------------------------------------
extern "C" void kernel_launch(void* const* d_in, const int* in_sizes, int n_in,
                              void* d_out, int out_size) {
    const float* x   = (const float*)d_in[0];
    const void*  ei  = d_in[1];
    const float* Wl1 = (const float*)d_in[2];
    const float* Wr1 = (const float*)d_in[3];
    const float* b1  = (const float*)d_in[4];
    const float* Wl2 = (const float*)d_in[5];
    const float* Wr2 = (const float*)d_in[6];
    const float* b2  = (const float*)d_in[7];
    float*       out = (float*)d_out;

    float *sums1, *sums2, *hbuf, *cnt;
    cudaGetSymbolAddress((void**)&sums1, g_sums1);
    cudaGetSymbolAddress((void**)&sums2, g_sums2);
    cudaGetSymbolAddress((void**)&hbuf,  g_h);
    cudaGetSymbolAddress((void**)&cnt,   g_cnt);

    // smem: K*JP (W) + K*TM (U) + JP bias, floats
    const int SMEM1 = (256 * 128 + 256 * 64  + 128) * 4;   // 197,120 B
    const int SMEM2 = (256 * 64  + 256 * 128 + 64)  * 4;   // 196,864 B
    cudaFuncSetAttribute(layer_kernel<64, 128, 128, true>,
                         cudaFuncAttributeMaxDynamicSharedMemorySize, SMEM1);
    cudaFuncSetAttribute(layer_kernel<128, 64, 40, false>,
                         cudaFuncAttributeMaxDynamicSharedMemorySize, SMEM2);

    // 0. detect index dtype (int32 vs int64)
    detect_kernel<<<1, 32>>>((const long long*)ei);

    // 1. zero accumulators + counts
    zero_kernel<<<2048, 256>>>();

    // 2. aggregate layer-1 neighbors (+ degree counts, computed once)
    scatter_kernel<<<(N_EDGES * 32) / 256, 256>>>(x, ei, sums1, cnt);

    // 3. h = relu([agg|x] @ [Wl1;Wr1] + b1)
    layer_kernel<64, 128, 128, true><<<152, 256, SMEM1>>>(sums1, cnt, x, Wl1, Wr1, b1, hbuf);

    // 4. aggregate layer-2 neighbors (counts reused)
    scatter_kernel<<<(N_EDGES * 32) / 256, 256>>>(hbuf, ei, sums2, nullptr);

    // 5. out = [agg2|h] @ [Wl2;Wr2] + b2
    layer_kernel<128, 64, 40, false><<<152, 256, SMEM2>>>(sums2, cnt, hbuf, Wl2, Wr2, b2, out);
}

// round 11
// speedup vs baseline: 1.2474x; 1.1906x over previous
#include <cuda_runtime.h>
#include <stdint.h>

#define N_NODES 50000
#define N_EDGES 800000
#define FEAT    128

typedef unsigned long long u64;

// Scratch (static device globals; no allocation allowed)
__device__ float g_sums1[(size_t)N_NODES * FEAT];
__device__ float g_sums2[(size_t)N_NODES * FEAT];
__device__ float g_h[(size_t)N_NODES * FEAT];
__device__ float g_cnt[N_NODES];
__device__ int   g_idx_is32;

// ---------------------------------------------------------------------------
// Detect edge_index dtype (reference says int64; JAX x64-off emits int32).
// ---------------------------------------------------------------------------
__global__ void detect_kernel(const long long* __restrict__ ei) {
    if (threadIdx.x == 0 && blockIdx.x == 0) {
        int is32 = 0;
        for (int i = 0; i < 64; i++) {
            long long v = ei[i];
            if (v < 0 || v >= N_NODES) { is32 = 1; break; }
        }
        g_idx_is32 = is32;
    }
}

// ---------------------------------------------------------------------------
// Zero the accumulators (replay-safe)
// ---------------------------------------------------------------------------
__global__ void zero_kernel() {
    const int total4 = (N_NODES * FEAT) / 4;
    int tid = blockIdx.x * blockDim.x + threadIdx.x;
    int stride = gridDim.x * blockDim.x;
    float4 z = make_float4(0.f, 0.f, 0.f, 0.f);
    for (int i = tid; i < total4; i += stride) {
        ((float4*)g_sums1)[i] = z;
        ((float4*)g_sums2)[i] = z;
    }
    for (int i = tid; i < N_NODES; i += stride) g_cnt[i] = 0.f;
}

// ---------------------------------------------------------------------------
// Edge scatter: one warp per edge; coalesced 512B gather + red.v4 to L2.
// ---------------------------------------------------------------------------
__global__ void scatter_kernel(const float* __restrict__ src_feat,
                               const void* __restrict__ ei,
                               float* __restrict__ sums,
                               float* __restrict__ cnt) {
    int gw   = (blockIdx.x * blockDim.x + threadIdx.x) >> 5;
    int lane = threadIdx.x & 31;
    if (gw >= N_EDGES) return;

    int s, d;
    if (g_idx_is32) {
        const int* e32 = (const int*)ei;
        s = __ldg(&e32[gw]);
        d = __ldg(&e32[N_EDGES + gw]);
    } else {
        const long long* e64 = (const long long*)ei;
        s = (int)__ldg(&e64[gw]);
        d = (int)__ldg(&e64[N_EDGES + gw]);
    }

    const float4* sp = (const float4*)(src_feat + (int64_t)s * FEAT);
    float4 v = __ldg(&sp[lane]);

    float* dp = sums + (int64_t)d * FEAT + lane * 4;
    asm volatile("red.global.add.v4.f32 [%0], {%1, %2, %3, %4};"
                 :: "l"(dp), "f"(v.x), "f"(v.y), "f"(v.z), "f"(v.w)
                 : "memory");

    if (cnt != nullptr && lane == 0)
        atomicAdd(cnt + d, 1.0f);
}

// ---------------------------------------------------------------------------
// Fused SAGE layer as ONE register-tiled GEMM over concatenated depth K=256:
//   U[n] = [ sums[n]/max(cnt,1) , xroot[n] ],  W = [Wl; Wr],  out = act(U W + b)
//
// 256 threads, 1 CTA/SM. Thread tile: NPT nodes x 8 cols, cols split as two
// contiguous float4 groups at {tc*4} and {JP/2 + tc*4}  -> LDS.128 lane
// stride 16B = conflict-free. Math in packed f32x2 (fma.rn.f32x2): column
// pairs come packed straight out of the float4 weight loads; node value is
// duplicated via mov.b64 {r,r}. sU staged transposed [k][m] in K-chunks of KC.
// ---------------------------------------------------------------------------
template <int TM, int JP, int JREAL, int KC, bool RELU>
__global__ void __launch_bounds__(256, 1)
layer_kernel(const float* __restrict__ sums, const float* __restrict__ cnt,
             const float* __restrict__ xroot,
             const float* __restrict__ Wl, const float* __restrict__ Wr,
             const float* __restrict__ bias, float* __restrict__ out) {
    constexpr int K   = 256;
    constexpr int KH  = 128;
    constexpr int NCG = JP / 8;        // col groups (8 cols each)
    constexpr int NNG = 256 / NCG;     // node groups
    constexpr int NPT = TM / NNG;      // nodes per thread (8 or 4)
    constexpr int NCHUNK = K / KC;
    static_assert(NPT == 8 || NPT == 4, "");

    extern __shared__ float smem[];
    float* sW = smem;              // K*JP   [k][j]
    float* sU = sW + K * JP;       // KC*TM  [k][m] transposed, chunked
    float* sb = sU + KC * TM;      // JP

    const int t = threadIdx.x;

    // Stage concatenated weights once (zero-padded cols)
    for (int idx = t; idx < KH * JP; idx += 256) {
        int k = idx / JP, j = idx % JP;
        float wl = 0.f, wr = 0.f;
        if (j < JREAL) {
            wl = __ldg(&Wl[k * JREAL + j]);
            wr = __ldg(&Wr[k * JREAL + j]);
        }
        sW[k * JP + j]        = wl;
        sW[(k + KH) * JP + j] = wr;
    }
    for (int idx = t; idx < JP; idx += 256)
        sb[idx] = (idx < JREAL) ? __ldg(&bias[idx]) : 0.f;

    const int tc = t % NCG;            // col group
    const int tn = t / NCG;            // node group
    const int c0 = tc * 4;             // first  float4 col base
    const int c1 = JP / 2 + tc * 4;    // second float4 col base
    const int ntiles = (N_NODES + TM - 1) / TM;

    for (int tile = blockIdx.x; tile < ntiles; tile += gridDim.x) {
        const int base = tile * TM;

        u64 acc[NPT][4];               // [node][colpair]; pairs 0-1 = c0 grp, 2-3 = c1 grp
#pragma unroll
        for (int p = 0; p < NPT; p++)
#pragma unroll
            for (int q = 0; q < 4; q++) acc[p][q] = 0ull;

#pragma unroll
        for (int kc = 0; kc < NCHUNK; kc++) {
            __syncthreads();           // previous chunk's mainloop done
            // Stage sU chunk transposed: lanes walk m -> conflict-free STS
            for (int idx = t; idx < (KC / 4) * TM; idx += 256) {
                int kk4 = idx / TM, m = idx % TM;
                int k4  = kc * (KC / 4) + kk4;
                int node = min(base + m, N_NODES - 1);
                float4 v;
                if (k4 < KH / 4) {
                    v = __ldg((const float4*)(sums + (int64_t)node * FEAT) + k4);
                    float inv = 1.0f / fmaxf(__ldg(&cnt[node]), 1.0f);
                    v.x *= inv; v.y *= inv; v.z *= inv; v.w *= inv;
                } else {
                    v = __ldg((const float4*)(xroot + (int64_t)node * FEAT) + (k4 - KH / 4));
                }
                int kr = kk4 * 4;
                sU[(kr + 0) * TM + m] = v.x;
                sU[(kr + 1) * TM + m] = v.y;
                sU[(kr + 2) * TM + m] = v.z;
                sU[(kr + 3) * TM + m] = v.w;
            }
            __syncthreads();

#pragma unroll 4
            for (int k = 0; k < KC; k++) {
                // weights: two conflict-free LDS.128, each = 2 packed col-pairs
                const u64* wp0 = (const u64*)(sW + (kc * KC + k) * JP + c0);
                const u64* wp1 = (const u64*)(sW + (kc * KC + k) * JP + c1);
                u64 w00 = wp0[0], w01 = wp0[1];
                u64 w10 = wp1[0], w11 = wp1[1];

                // node values (broadcast LDS.128)
                const float* ap = sU + k * TM + tn * NPT;
                float4 a0 = *(const float4*)ap;
                float av[NPT];
                av[0] = a0.x; av[1] = a0.y; av[2] = a0.z; av[3] = a0.w;
                if (NPT == 8) {
                    float4 a1 = *(const float4*)(ap + 4);
                    av[4] = a1.x; av[5] = a1.y; av[6] = a1.z; av[7] = a1.w;
                }

                u64 ad[NPT];
#pragma unroll
                for (int p = 0; p < NPT; p++)
                    asm("mov.b64 %0, {%1, %1};" : "=l"(ad[p]) : "f"(av[p]));
#pragma unroll
                for (int p = 0; p < NPT; p++) {
                    asm("fma.rn.f32x2 %0, %1, %2, %0;" : "+l"(acc[p][0]) : "l"(ad[p]), "l"(w00));
                    asm("fma.rn.f32x2 %0, %1, %2, %0;" : "+l"(acc[p][1]) : "l"(ad[p]), "l"(w01));
                    asm("fma.rn.f32x2 %0, %1, %2, %0;" : "+l"(acc[p][2]) : "l"(ad[p]), "l"(w10));
                    asm("fma.rn.f32x2 %0, %1, %2, %0;" : "+l"(acc[p][3]) : "l"(ad[p]), "l"(w11));
                }
            }
        }

        // Epilogue: unpack, bias, act, store (two float4 groups per node)
        float4 b0 = *(const float4*)(sb + c0);
        float4 b1 = *(const float4*)(sb + c1);
#pragma unroll
        for (int p = 0; p < NPT; p++) {
            int node = base + tn * NPT + p;
            if (node >= N_NODES) continue;
            float r[8];
#pragma unroll
            for (int q = 0; q < 4; q++)
                asm("mov.b64 {%0, %1}, %2;" : "=f"(r[q * 2]), "=f"(r[q * 2 + 1]) : "l"(acc[p][q]));
            r[0] += b0.x; r[1] += b0.y; r[2] += b0.z; r[3] += b0.w;
            r[4] += b1.x; r[5] += b1.y; r[6] += b1.z; r[7] += b1.w;
            if (RELU) {
#pragma unroll
                for (int q = 0; q < 8; q++) r[q] = fmaxf(r[q], 0.f);
            }
            float* op = out + (int64_t)node * JREAL;
            if (c0 + 3 < JREAL)
                *(float4*)(op + c0) = make_float4(r[0], r[1], r[2], r[3]);
            if (c1 + 3 < JREAL)
                *(float4*)(op + c1) = make_float4(r[4], r[5], r[6], r[7]);
        }
    }
}

// ---------------------------------------------------------------------------
extern "C" void kernel_launch(void* const* d_in, const int* in_sizes, int n_in,
                              void* d_out, int out_size) {
    const float* x   = (const float*)d_in[0];
    const void*  ei  = d_in[1];
    const float* Wl1 = (const float*)d_in[2];
    const float* Wr1 = (const float*)d_in[3];
    const float* b1  = (const float*)d_in[4];
    const float* Wl2 = (const float*)d_in[5];
    const float* Wr2 = (const float*)d_in[6];
    const float* b2  = (const float*)d_in[7];
    float*       out = (float*)d_out;

    float *sums1, *sums2, *hbuf, *cnt;
    cudaGetSymbolAddress((void**)&sums1, g_sums1);
    cudaGetSymbolAddress((void**)&sums2, g_sums2);
    cudaGetSymbolAddress((void**)&hbuf,  g_h);
    cudaGetSymbolAddress((void**)&cnt,   g_cnt);

    // Layer1: TM=128, JP=128, KC=128 -> sW 128KB + sU 64KB + bias
    // Layer2: TM=128, JP=64,  KC=256 -> sW 64KB  + sU 128KB + bias
    const int SMEM1 = (256 * 128 + 128 * 128 + 128) * 4;
    const int SMEM2 = (256 * 64  + 256 * 128 + 64)  * 4;
    cudaFuncSetAttribute(layer_kernel<128, 128, 128, 128, true>,
                         cudaFuncAttributeMaxDynamicSharedMemorySize, SMEM1);
    cudaFuncSetAttribute(layer_kernel<128, 64, 40, 256, false>,
                         cudaFuncAttributeMaxDynamicSharedMemorySize, SMEM2);

    // 0. detect index dtype (int32 vs int64)
    detect_kernel<<<1, 32>>>((const long long*)ei);

    // 1. zero accumulators + counts
    zero_kernel<<<2048, 256>>>();

    // 2. aggregate layer-1 neighbors (+ degree counts, computed once)
    scatter_kernel<<<(N_EDGES * 32) / 256, 256>>>(x, ei, sums1, cnt);

    // 3. h = relu([agg|x] @ [Wl1;Wr1] + b1)
    layer_kernel<128, 128, 128, 128, true><<<152, 256, SMEM1>>>(sums1, cnt, x, Wl1, Wr1, b1, hbuf);

    // 4. aggregate layer-2 neighbors (counts reused)
    scatter_kernel<<<(N_EDGES * 32) / 256, 256>>>(hbuf, ei, sums2, nullptr);

    // 5. out = [agg2|h] @ [Wl2;Wr2] + b2
    layer_kernel<128, 64, 40, 256, false><<<152, 256, SMEM2>>>(sums2, cnt, hbuf, Wl2, Wr2, b2, out);
}

// round 14
// speedup vs baseline: 1.8813x; 1.5081x over previous
#include <cuda_runtime.h>
#include <stdint.h>

#define N_NODES 50000
#define N_EDGES 800000
#define FEAT    128
#define NBLK    ((N_NODES + 255) / 256)   // 196 scan blocks

typedef unsigned long long u64;

// Scratch (static device globals; no allocation allowed)
__device__ float g_mean1[(size_t)N_NODES * FEAT];
__device__ float g_mean2[(size_t)N_NODES * FEAT];
__device__ float g_h[(size_t)N_NODES * FEAT];
__device__ int   g_deg[N_NODES];
__device__ int   g_row[N_NODES + 1];
__device__ int   g_cursor[N_NODES];
__device__ int   g_csr[N_EDGES];
__device__ int   g_partials[NBLK];
__device__ int   g_idx_is32;

// ---------------------------------------------------------------------------
// Detect edge_index dtype (reference says int64; JAX x64-off emits int32).
// ---------------------------------------------------------------------------
__global__ void detect_kernel(const long long* __restrict__ ei) {
    if (threadIdx.x == 0 && blockIdx.x == 0) {
        int is32 = 0;
        for (int i = 0; i < 64; i++) {
            long long v = ei[i];
            if (v < 0 || v >= N_NODES) { is32 = 1; break; }
        }
        g_idx_is32 = is32;
    }
}

__device__ __forceinline__ int load_src(const void* ei, int e) {
    return g_idx_is32 ? __ldg(&((const int*)ei)[e])
                      : (int)__ldg(&((const long long*)ei)[e]);
}
__device__ __forceinline__ int load_dst(const void* ei, int e) {
    return g_idx_is32 ? __ldg(&((const int*)ei)[N_EDGES + e])
                      : (int)__ldg(&((const long long*)ei)[N_EDGES + e]);
}

// ---------------------------------------------------------------------------
// CSR build: zero counters -> histogram -> 2-level exclusive scan -> fill
// ---------------------------------------------------------------------------
__global__ void zero_deg_kernel() {
    int i = blockIdx.x * blockDim.x + threadIdx.x;
    if (i < N_NODES) g_deg[i] = 0;
}

__global__ void hist_kernel(const void* __restrict__ ei) {
    int e = blockIdx.x * blockDim.x + threadIdx.x;
    if (e < N_EDGES) atomicAdd(&g_deg[load_dst(ei, e)], 1);
}

__global__ void scan1_kernel() {                    // per-block sums
    __shared__ int sh[256];
    int i = blockIdx.x * 256 + threadIdx.x;
    int v = (i < N_NODES) ? g_deg[i] : 0;
    sh[threadIdx.x] = v;
    __syncthreads();
    for (int o = 128; o > 0; o >>= 1) {
        if (threadIdx.x < o) sh[threadIdx.x] += sh[threadIdx.x + o];
        __syncthreads();
    }
    if (threadIdx.x == 0) g_partials[blockIdx.x] = sh[0];
}

__global__ void scan2_kernel() {                    // scan of 196 partials
    if (threadIdx.x == 0 && blockIdx.x == 0) {
        int run = 0;
        for (int b = 0; b < NBLK; b++) {
            int t = g_partials[b];
            g_partials[b] = run;
            run += t;
        }
        g_row[N_NODES] = N_EDGES;
    }
}

__global__ void scan3_kernel() {                    // row_ptr + cursor init
    __shared__ int sh[256];
    int i = blockIdx.x * 256 + threadIdx.x;
    int v = (i < N_NODES) ? g_deg[i] : 0;
    sh[threadIdx.x] = v;
    __syncthreads();
    // Hillis-Steele inclusive scan
    for (int o = 1; o < 256; o <<= 1) {
        int add = (threadIdx.x >= o) ? sh[threadIdx.x - o] : 0;
        __syncthreads();
        sh[threadIdx.x] += add;
        __syncthreads();
    }
    if (i < N_NODES) {
        int excl = sh[threadIdx.x] - v + g_partials[blockIdx.x];
        g_row[i] = excl;
        g_cursor[i] = excl;
    }
}

__global__ void fill_kernel(const void* __restrict__ ei) {
    int e = blockIdx.x * blockDim.x + threadIdx.x;
    if (e < N_EDGES) {
        int d = load_dst(ei, e);
        int pos = atomicAdd(&g_cursor[d], 1);
        g_csr[pos] = load_src(ei, e);
    }
}

// ---------------------------------------------------------------------------
// CSR mean-aggregation: one warp per dst node, lane = float4 slice.
// Register accumulation, single write of the MEAN row. No atomics, no zeroing.
// 4-edge unroll -> 4 independent 512B row reads in flight per warp (MLP).
// ---------------------------------------------------------------------------
__global__ void __launch_bounds__(256)
aggregate_kernel(const float* __restrict__ feat, float* __restrict__ outm) {
    int w    = (blockIdx.x * blockDim.x + threadIdx.x) >> 5;
    int lane = threadIdx.x & 31;
    if (w >= N_NODES) return;

    int start = __ldg(&g_row[w]);
    int end   = __ldg(&g_row[w + 1]);

    float4 acc = make_float4(0.f, 0.f, 0.f, 0.f);
    int i = start;
    for (; i + 4 <= end; i += 4) {
        int s0 = __ldg(&g_csr[i]);
        int s1 = __ldg(&g_csr[i + 1]);
        int s2 = __ldg(&g_csr[i + 2]);
        int s3 = __ldg(&g_csr[i + 3]);
        float4 v0 = __ldg((const float4*)(feat + (size_t)s0 * FEAT) + lane);
        float4 v1 = __ldg((const float4*)(feat + (size_t)s1 * FEAT) + lane);
        float4 v2 = __ldg((const float4*)(feat + (size_t)s2 * FEAT) + lane);
        float4 v3 = __ldg((const float4*)(feat + (size_t)s3 * FEAT) + lane);
        acc.x += (v0.x + v1.x) + (v2.x + v3.x);
        acc.y += (v0.y + v1.y) + (v2.y + v3.y);
        acc.z += (v0.z + v1.z) + (v2.z + v3.z);
        acc.w += (v0.w + v1.w) + (v2.w + v3.w);
    }
    for (; i < end; i++) {
        int s = __ldg(&g_csr[i]);
        float4 v = __ldg((const float4*)(feat + (size_t)s * FEAT) + lane);
        acc.x += v.x; acc.y += v.y; acc.z += v.z; acc.w += v.w;
    }
    float inv = 1.0f / fmaxf((float)(end - start), 1.0f);
    acc.x *= inv; acc.y *= inv; acc.z *= inv; acc.w *= inv;
    ((float4*)(outm + (size_t)w * FEAT))[lane] = acc;
}

// ---------------------------------------------------------------------------
// Fused SAGE layer GEMM over concatenated depth K=256 (mean precomputed):
//   U[n] = [ mean[n] , xroot[n] ],  W = [Wl; Wr],  out = act(U W + b)
// 256 threads, 1 CTA/SM, f32x2 packed math, conflict-free LDS (two contiguous
// float4 col groups at tc*4 and JP/2+tc*4).
// ---------------------------------------------------------------------------
template <int TM, int JP, int JREAL, int KC, bool RELU>
__global__ void __launch_bounds__(256, 1)
layer_kernel(const float* __restrict__ mean, const float* __restrict__ xroot,
             const float* __restrict__ Wl, const float* __restrict__ Wr,
             const float* __restrict__ bias, float* __restrict__ out) {
    constexpr int K   = 256;
    constexpr int KH  = 128;
    constexpr int NCG = JP / 8;
    constexpr int NNG = 256 / NCG;
    constexpr int NPT = TM / NNG;
    constexpr int NCHUNK = K / KC;
    static_assert(NPT == 8 || NPT == 4, "");

    extern __shared__ float smem[];
    float* sW = smem;              // K*JP   [k][j]
    float* sU = sW + K * JP;       // KC*TM  [k][m] transposed, chunked
    float* sb = sU + KC * TM;      // JP

    const int t = threadIdx.x;

    for (int idx = t; idx < KH * JP; idx += 256) {
        int k = idx / JP, j = idx % JP;
        float wl = 0.f, wr = 0.f;
        if (j < JREAL) {
            wl = __ldg(&Wl[k * JREAL + j]);
            wr = __ldg(&Wr[k * JREAL + j]);
        }
        sW[k * JP + j]        = wl;
        sW[(k + KH) * JP + j] = wr;
    }
    for (int idx = t; idx < JP; idx += 256)
        sb[idx] = (idx < JREAL) ? __ldg(&bias[idx]) : 0.f;

    const int tc = t % NCG;
    const int tn = t / NCG;
    const int c0 = tc * 4;
    const int c1 = JP / 2 + tc * 4;
    const int ntiles = (N_NODES + TM - 1) / TM;

    for (int tile = blockIdx.x; tile < ntiles; tile += gridDim.x) {
        const int base = tile * TM;

        u64 acc[NPT][4];
#pragma unroll
        for (int p = 0; p < NPT; p++)
#pragma unroll
            for (int q = 0; q < 4; q++) acc[p][q] = 0ull;

#pragma unroll
        for (int kc = 0; kc < NCHUNK; kc++) {
            __syncthreads();
            for (int idx = t; idx < (KC / 4) * TM; idx += 256) {
                int kk4 = idx / TM, m = idx % TM;
                int k4  = kc * (KC / 4) + kk4;
                int node = min(base + m, N_NODES - 1);
                float4 v;
                if (k4 < KH / 4)
                    v = __ldg((const float4*)(mean + (int64_t)node * FEAT) + k4);
                else
                    v = __ldg((const float4*)(xroot + (int64_t)node * FEAT) + (k4 - KH / 4));
                int kr = kk4 * 4;
                sU[(kr + 0) * TM + m] = v.x;
                sU[(kr + 1) * TM + m] = v.y;
                sU[(kr + 2) * TM + m] = v.z;
                sU[(kr + 3) * TM + m] = v.w;
            }
            __syncthreads();

#pragma unroll 4
            for (int k = 0; k < KC; k++) {
                const u64* wp0 = (const u64*)(sW + (kc * KC + k) * JP + c0);
                const u64* wp1 = (const u64*)(sW + (kc * KC + k) * JP + c1);
                u64 w00 = wp0[0], w01 = wp0[1];
                u64 w10 = wp1[0], w11 = wp1[1];

                const float* ap = sU + k * TM + tn * NPT;
                float4 a0 = *(const float4*)ap;
                float av[NPT];
                av[0] = a0.x; av[1] = a0.y; av[2] = a0.z; av[3] = a0.w;
                if (NPT == 8) {
                    float4 a1 = *(const float4*)(ap + 4);
                    av[4] = a1.x; av[5] = a1.y; av[6] = a1.z; av[7] = a1.w;
                }

                u64 ad[NPT];
#pragma unroll
                for (int p = 0; p < NPT; p++)
                    asm("mov.b64 %0, {%1, %1};" : "=l"(ad[p]) : "f"(av[p]));
#pragma unroll
                for (int p = 0; p < NPT; p++) {
                    asm("fma.rn.f32x2 %0, %1, %2, %0;" : "+l"(acc[p][0]) : "l"(ad[p]), "l"(w00));
                    asm("fma.rn.f32x2 %0, %1, %2, %0;" : "+l"(acc[p][1]) : "l"(ad[p]), "l"(w01));
                    asm("fma.rn.f32x2 %0, %1, %2, %0;" : "+l"(acc[p][2]) : "l"(ad[p]), "l"(w10));
                    asm("fma.rn.f32x2 %0, %1, %2, %0;" : "+l"(acc[p][3]) : "l"(ad[p]), "l"(w11));
                }
            }
        }

        float4 b0 = *(const float4*)(sb + c0);
        float4 b1 = *(const float4*)(sb + c1);
#pragma unroll
        for (int p = 0; p < NPT; p++) {
            int node = base + tn * NPT + p;
            if (node >= N_NODES) continue;
            float r[8];
#pragma unroll
            for (int q = 0; q < 4; q++)
                asm("mov.b64 {%0, %1}, %2;" : "=f"(r[q * 2]), "=f"(r[q * 2 + 1]) : "l"(acc[p][q]));
            r[0] += b0.x; r[1] += b0.y; r[2] += b0.z; r[3] += b0.w;
            r[4] += b1.x; r[5] += b1.y; r[6] += b1.z; r[7] += b1.w;
            if (RELU) {
#pragma unroll
                for (int q = 0; q < 8; q++) r[q] = fmaxf(r[q], 0.f);
            }
            float* op = out + (int64_t)node * JREAL;
            if (c0 + 3 < JREAL)
                *(float4*)(op + c0) = make_float4(r[0], r[1], r[2], r[3]);
            if (c1 + 3 < JREAL)
                *(float4*)(op + c1) = make_float4(r[4], r[5], r[6], r[7]);
        }
    }
}

// ---------------------------------------------------------------------------
extern "C" void kernel_launch(void* const* d_in, const int* in_sizes, int n_in,
                              void* d_out, int out_size) {
    const float* x   = (const float*)d_in[0];
    const void*  ei  = d_in[1];
    const float* Wl1 = (const float*)d_in[2];
    const float* Wr1 = (const float*)d_in[3];
    const float* b1  = (const float*)d_in[4];
    const float* Wl2 = (const float*)d_in[5];
    const float* Wr2 = (const float*)d_in[6];
    const float* b2  = (const float*)d_in[7];
    float*       out = (float*)d_out;

    float *mean1, *mean2, *hbuf;
    cudaGetSymbolAddress((void**)&mean1, g_mean1);
    cudaGetSymbolAddress((void**)&mean2, g_mean2);
    cudaGetSymbolAddress((void**)&hbuf,  g_h);

    const int SMEM1 = (256 * 128 + 128 * 128 + 128) * 4;
    const int SMEM2 = (256 * 64  + 256 * 128 + 64)  * 4;
    cudaFuncSetAttribute(layer_kernel<128, 128, 128, 128, true>,
                         cudaFuncAttributeMaxDynamicSharedMemorySize, SMEM1);
    cudaFuncSetAttribute(layer_kernel<128, 64, 40, 256, false>,
                         cudaFuncAttributeMaxDynamicSharedMemorySize, SMEM2);

    const int EB = (N_EDGES + 255) / 256;

    // 0. detect index dtype; build CSR (per replay — deterministic)
    detect_kernel<<<1, 32>>>((const long long*)ei);
    zero_deg_kernel<<<NBLK, 256>>>();
    hist_kernel<<<EB, 256>>>(ei);
    scan1_kernel<<<NBLK, 256>>>();
    scan2_kernel<<<1, 32>>>();
    scan3_kernel<<<NBLK, 256>>>();
    fill_kernel<<<EB, 256>>>(ei);

    // 1. mean-aggregate layer-1 neighbors (CSR gather, no atomics)
    aggregate_kernel<<<(N_NODES * 32 + 255) / 256, 256>>>(x, mean1);

    // 2. h = relu([mean1|x] @ [Wl1;Wr1] + b1)
    layer_kernel<128, 128, 128, 128, true><<<152, 256, SMEM1>>>(mean1, x, Wl1, Wr1, b1, hbuf);

    // 3. mean-aggregate layer-2 neighbors
    aggregate_kernel<<<(N_NODES * 32 + 255) / 256, 256>>>(hbuf, mean2);

    // 4. out = [mean2|h] @ [Wl2;Wr2] + b2
    layer_kernel<128, 64, 40, 256, false><<<152, 256, SMEM2>>>(mean2, hbuf, Wl2, Wr2, b2, out);
}

// round 16
// speedup vs baseline: 2.4428x; 1.2985x over previous
#include <cuda_runtime.h>
#include <stdint.h>

#define N_NODES 50000
#define N_EDGES 800000
#define FEAT    128
#define NBLK    ((N_NODES + 255) / 256)   // 196 scan blocks

typedef unsigned long long u64;
typedef unsigned int uint;

// Scratch (static device globals; no allocation allowed)
__device__ float g_mean1[(size_t)N_NODES * FEAT];
__device__ float g_mean2[(size_t)N_NODES * FEAT];
__device__ float g_h[(size_t)N_NODES * FEAT];
__device__ int   g_deg[N_NODES];
__device__ int   g_row[N_NODES + 1];
__device__ int   g_cursor[N_NODES];
__device__ int   g_csr[N_EDGES];
__device__ int   g_partials[NBLK];
__device__ int   g_idx_is32;

// ---------------------------------------------------------------------------
// Detect edge_index dtype (reference says int64; JAX x64-off emits int32).
// ---------------------------------------------------------------------------
__global__ void detect_kernel(const long long* __restrict__ ei) {
    if (threadIdx.x == 0 && blockIdx.x == 0) {
        int is32 = 0;
        for (int i = 0; i < 64; i++) {
            long long v = ei[i];
            if (v < 0 || v >= N_NODES) { is32 = 1; break; }
        }
        g_idx_is32 = is32;
    }
}

__device__ __forceinline__ int load_src(const void* ei, int e) {
    return g_idx_is32 ? __ldg(&((const int*)ei)[e])
                      : (int)__ldg(&((const long long*)ei)[e]);
}
__device__ __forceinline__ int load_dst(const void* ei, int e) {
    return g_idx_is32 ? __ldg(&((const int*)ei)[N_EDGES + e])
                      : (int)__ldg(&((const long long*)ei)[N_EDGES + e]);
}

// ---------------------------------------------------------------------------
// CSR build: zero counters -> histogram -> 2-level exclusive scan -> fill
// ---------------------------------------------------------------------------
__global__ void zero_deg_kernel() {
    int i = blockIdx.x * blockDim.x + threadIdx.x;
    if (i < N_NODES) g_deg[i] = 0;
}

__global__ void hist_kernel(const void* __restrict__ ei) {
    int e = blockIdx.x * blockDim.x + threadIdx.x;
    if (e < N_EDGES) atomicAdd(&g_deg[load_dst(ei, e)], 1);
}

__global__ void scan1_kernel() {                    // per-block sums
    __shared__ int sh[256];
    int i = blockIdx.x * 256 + threadIdx.x;
    int v = (i < N_NODES) ? g_deg[i] : 0;
    sh[threadIdx.x] = v;
    __syncthreads();
    for (int o = 128; o > 0; o >>= 1) {
        if (threadIdx.x < o) sh[threadIdx.x] += sh[threadIdx.x + o];
        __syncthreads();
    }
    if (threadIdx.x == 0) g_partials[blockIdx.x] = sh[0];
}

__global__ void scan2_kernel() {                    // scan of 196 partials
    if (threadIdx.x == 0 && blockIdx.x == 0) {
        int run = 0;
        for (int b = 0; b < NBLK; b++) {
            int t = g_partials[b];
            g_partials[b] = run;
            run += t;
        }
        g_row[N_NODES] = N_EDGES;
    }
}

__global__ void scan3_kernel() {                    // row_ptr + cursor init
    __shared__ int sh[256];
    int i = blockIdx.x * 256 + threadIdx.x;
    int v = (i < N_NODES) ? g_deg[i] : 0;
    sh[threadIdx.x] = v;
    __syncthreads();
    for (int o = 1; o < 256; o <<= 1) {
        int add = (threadIdx.x >= o) ? sh[threadIdx.x - o] : 0;
        __syncthreads();
        sh[threadIdx.x] += add;
        __syncthreads();
    }
    if (i < N_NODES) {
        int excl = sh[threadIdx.x] - v + g_partials[blockIdx.x];
        g_row[i] = excl;
        g_cursor[i] = excl;
    }
}

__global__ void fill_kernel(const void* __restrict__ ei) {
    int e = blockIdx.x * blockDim.x + threadIdx.x;
    if (e < N_EDGES) {
        int d = load_dst(ei, e);
        int pos = atomicAdd(&g_cursor[d], 1);
        g_csr[pos] = load_src(ei, e);
    }
}

// ---------------------------------------------------------------------------
// CSR mean-aggregation: one warp per dst node, lane = float4 slice.
// ---------------------------------------------------------------------------
__global__ void __launch_bounds__(256)
aggregate_kernel(const float* __restrict__ feat, float* __restrict__ outm) {
    int w    = (blockIdx.x * blockDim.x + threadIdx.x) >> 5;
    int lane = threadIdx.x & 31;
    if (w >= N_NODES) return;

    int start = __ldg(&g_row[w]);
    int end   = __ldg(&g_row[w + 1]);

    float4 acc = make_float4(0.f, 0.f, 0.f, 0.f);
    int i = start;
    for (; i + 4 <= end; i += 4) {
        int s0 = __ldg(&g_csr[i]);
        int s1 = __ldg(&g_csr[i + 1]);
        int s2 = __ldg(&g_csr[i + 2]);
        int s3 = __ldg(&g_csr[i + 3]);
        float4 v0 = __ldg((const float4*)(feat + (size_t)s0 * FEAT) + lane);
        float4 v1 = __ldg((const float4*)(feat + (size_t)s1 * FEAT) + lane);
        float4 v2 = __ldg((const float4*)(feat + (size_t)s2 * FEAT) + lane);
        float4 v3 = __ldg((const float4*)(feat + (size_t)s3 * FEAT) + lane);
        acc.x += (v0.x + v1.x) + (v2.x + v3.x);
        acc.y += (v0.y + v1.y) + (v2.y + v3.y);
        acc.z += (v0.z + v1.z) + (v2.z + v3.z);
        acc.w += (v0.w + v1.w) + (v2.w + v3.w);
    }
    for (; i < end; i++) {
        int s = __ldg(&g_csr[i]);
        float4 v = __ldg((const float4*)(feat + (size_t)s * FEAT) + lane);
        acc.x += v.x; acc.y += v.y; acc.z += v.z; acc.w += v.w;
    }
    float inv = 1.0f / fmaxf((float)(end - start), 1.0f);
    acc.x *= inv; acc.y *= inv; acc.z *= inv; acc.w *= inv;
    ((float4*)(outm + (size_t)w * FEAT))[lane] = acc;
}

// ---------------------------------------------------------------------------
// SAGE layer via TF32 tensor cores (mma.sync m16n8k8):
//   U[n] = [ mean[n] , xroot[n] ]  (K=256),  W = [Wl; Wr],  out = act(U W + b)
//
// 256 threads (8 warps), 1 CTA/SM, persistent. Warp tile 32x32:
//   2 m-tiles (16) x NT_W=4 n-tiles (8) = 8 MMAs per k8-step, 32 k8-steps.
// sB holds W pre-arranged in exact B-fragment order [kk][jt][lane][2] (tf32),
//   so mainloop B load = 1x ld.shared.v2, conflict-free.
// sU is [m][k] with stride 260 (mod 32 = 4) -> A-frag LDS.32 lanes hit banks
//   4g+t4 = all distinct -> conflict-free.
// ---------------------------------------------------------------------------
template <int TM, int JP, int JREAL, bool RELU>
__global__ void __launch_bounds__(256, 1)
layer_mma(const float* __restrict__ mean, const float* __restrict__ xroot,
          const float* __restrict__ Wl, const float* __restrict__ Wr,
          const float* __restrict__ bias, float* __restrict__ out) {
    constexpr int K    = 256;
    constexpr int KK   = K / 8;        // 32 k8-steps
    constexpr int WM   = TM / 32;      // warps along M
    constexpr int WN   = 8 / WM;       // warps along N
    constexpr int NJT  = JP / 8;       // total n-tiles
    constexpr int NT_W = NJT / WN;     // n-tiles per warp (=4)
    constexpr int SUS  = K + 4;        // sU stride: 260 (mod 32 == 4)
    static_assert(NT_W == 4, "");

    extern __shared__ uint sm[];
    uint*  sB = sm;                         // KK*NJT*64 u32 (fragment order)
    uint*  sU = sB + KK * NJT * 64;         // TM*SUS u32 (tf32 bits)
    float* sb = (float*)(sU + TM * SUS);    // JP

    const int t = threadIdx.x;

    // Stage B fragments once (tf32). b0 = W[kk*8+t4][jt*8+g], b1 = +4 k-rows.
    for (int idx = t; idx < KK * NJT * 32; idx += 256) {
        int lane = idx & 31, rem = idx >> 5;
        int jt = rem % NJT, kk = rem / NJT;
        int krow = kk * 8 + (lane & 3);
        int j    = jt * 8 + (lane >> 2);
        float w0 = 0.f, w1 = 0.f;
        if (j < JREAL) {
            w0 = (krow < 128) ? __ldg(&Wl[krow * JREAL + j])
                              : __ldg(&Wr[(krow - 128) * JREAL + j]);
            int k2 = krow + 4;   // stays inside the same 8-row block
            w1 = (k2 < 128) ? __ldg(&Wl[k2 * JREAL + j])
                            : __ldg(&Wr[(k2 - 128) * JREAL + j]);
        }
        uint u0, u1;
        asm("cvt.rna.tf32.f32 %0, %1;" : "=r"(u0) : "f"(w0));
        asm("cvt.rna.tf32.f32 %0, %1;" : "=r"(u1) : "f"(w1));
        sB[((kk * NJT + jt) * 32 + lane) * 2 + 0] = u0;
        sB[((kk * NJT + jt) * 32 + lane) * 2 + 1] = u1;
    }
    for (int idx = t; idx < JP; idx += 256)
        sb[idx] = (idx < JREAL) ? __ldg(&bias[idx]) : 0.f;

    const int wid = t >> 5, lane = t & 31;
    const int wm = wid % WM, wn = wid / WM;
    const int g = lane >> 2, t4 = lane & 3;
    const int ntiles = (N_NODES + TM - 1) / TM;

    for (int tile = blockIdx.x; tile < ntiles; tile += gridDim.x) {
        const int base = tile * TM;
        __syncthreads();   // previous tile fully consumed before restaging sU

        // Stage sU (tf32 bits). Lanes walk k4 -> conflict-free STS.128.
        for (int idx = t; idx < TM * (K / 4); idx += 256) {
            int k4 = idx & 63, m = idx >> 6;
            int node = min(base + m, N_NODES - 1);
            float4 v = (k4 < 32)
                ? __ldg((const float4*)(mean  + (size_t)node * FEAT) + k4)
                : __ldg((const float4*)(xroot + (size_t)node * FEAT) + (k4 - 32));
            uint4 u;
            asm("cvt.rna.tf32.f32 %0, %1;" : "=r"(u.x) : "f"(v.x));
            asm("cvt.rna.tf32.f32 %0, %1;" : "=r"(u.y) : "f"(v.y));
            asm("cvt.rna.tf32.f32 %0, %1;" : "=r"(u.z) : "f"(v.z));
            asm("cvt.rna.tf32.f32 %0, %1;" : "=r"(u.w) : "f"(v.w));
            *(uint4*)(sU + m * SUS + k4 * 4) = u;
        }
        __syncthreads();

        float acc[2][NT_W][4];
#pragma unroll
        for (int mt = 0; mt < 2; mt++)
#pragma unroll
            for (int nt = 0; nt < NT_W; nt++)
#pragma unroll
                for (int q = 0; q < 4; q++) acc[mt][nt][q] = 0.f;

#pragma unroll 4
        for (int kk = 0; kk < KK; kk++) {
            uint a[2][4];
#pragma unroll
            for (int mt = 0; mt < 2; mt++) {
                const uint* p = sU + (wm * 32 + mt * 16 + g) * SUS + kk * 8 + t4;
                a[mt][0] = p[0];
                a[mt][1] = p[8 * SUS];
                a[mt][2] = p[4];
                a[mt][3] = p[8 * SUS + 4];
            }
#pragma unroll
            for (int nt = 0; nt < NT_W; nt++) {
                int jt = wn * NT_W + nt;
                uint2 b = *(const uint2*)(sB + ((kk * NJT + jt) * 32 + lane) * 2);
#pragma unroll
                for (int mt = 0; mt < 2; mt++) {
                    asm("mma.sync.aligned.m16n8k8.row.col.f32.tf32.tf32.f32 "
                        "{%0,%1,%2,%3}, {%4,%5,%6,%7}, {%8,%9}, {%0,%1,%2,%3};"
                        : "+f"(acc[mt][nt][0]), "+f"(acc[mt][nt][1]),
                          "+f"(acc[mt][nt][2]), "+f"(acc[mt][nt][3])
                        : "r"(a[mt][0]), "r"(a[mt][1]), "r"(a[mt][2]), "r"(a[mt][3]),
                          "r"(b.x), "r"(b.y));
                }
            }
        }

        // Epilogue: bias + act + float2 stores (cols 2t4, 2t4+1 contiguous)
#pragma unroll
        for (int mt = 0; mt < 2; mt++) {
            int r0 = base + wm * 32 + mt * 16 + g;
            int r1 = r0 + 8;
#pragma unroll
            for (int nt = 0; nt < NT_W; nt++) {
                int j0 = (wn * NT_W + nt) * 8 + 2 * t4;
                if (j0 >= JREAL) continue;   // JREAL even -> pair all-or-none
                float bz0 = sb[j0], bz1 = sb[j0 + 1];
                float c0 = acc[mt][nt][0] + bz0, c1 = acc[mt][nt][1] + bz1;
                float c2 = acc[mt][nt][2] + bz0, c3 = acc[mt][nt][3] + bz1;
                if (RELU) {
                    c0 = fmaxf(c0, 0.f); c1 = fmaxf(c1, 0.f);
                    c2 = fmaxf(c2, 0.f); c3 = fmaxf(c3, 0.f);
                }
                if (r0 < N_NODES)
                    *(float2*)(out + (size_t)r0 * JREAL + j0) = make_float2(c0, c1);
                if (r1 < N_NODES)
                    *(float2*)(out + (size_t)r1 * JREAL + j0) = make_float2(c2, c3);
            }
        }
    }
}

// ---------------------------------------------------------------------------
extern "C" void kernel_launch(void* const* d_in, const int* in_sizes, int n_in,
                              void* d_out, int out_size) {
    const float* x   = (const float*)d_in[0];
    const void*  ei  = d_in[1];
    const float* Wl1 = (const float*)d_in[2];
    const float* Wr1 = (const float*)d_in[3];
    const float* b1  = (const float*)d_in[4];
    const float* Wl2 = (const float*)d_in[5];
    const float* Wr2 = (const float*)d_in[6];
    const float* b2  = (const float*)d_in[7];
    float*       out = (float*)d_out;

    float *mean1, *mean2, *hbuf;
    cudaGetSymbolAddress((void**)&mean1, g_mean1);
    cudaGetSymbolAddress((void**)&mean2, g_mean2);
    cudaGetSymbolAddress((void**)&hbuf,  g_h);

    // Layer1: TM=64, JP=128 -> sB 32*16*64 + sU 64*260 + sb 128 = 198,144 B
    // Layer2: TM=128, JP=64 -> sB 32*8*64  + sU 128*260 + sb 64 = 198,912 B
    const int SMEM1 = (32 * 16 * 64 + 64 * 260 + 128) * 4;
    const int SMEM2 = (32 * 8 * 64 + 128 * 260 + 64) * 4;
    cudaFuncSetAttribute(layer_mma<64, 128, 128, true>,
                         cudaFuncAttributeMaxDynamicSharedMemorySize, SMEM1);
    cudaFuncSetAttribute(layer_mma<128, 64, 40, false>,
                         cudaFuncAttributeMaxDynamicSharedMemorySize, SMEM2);

    const int EB = (N_EDGES + 255) / 256;

    // 0. detect index dtype; build CSR (per replay — deterministic)
    detect_kernel<<<1, 32>>>((const long long*)ei);
    zero_deg_kernel<<<NBLK, 256>>>();
    hist_kernel<<<EB, 256>>>(ei);
    scan1_kernel<<<NBLK, 256>>>();
    scan2_kernel<<<1, 32>>>();
    scan3_kernel<<<NBLK, 256>>>();
    fill_kernel<<<EB, 256>>>(ei);

    // 1. mean-aggregate layer-1 neighbors (CSR gather, no atomics)
    aggregate_kernel<<<(N_NODES * 32 + 255) / 256, 256>>>(x, mean1);

    // 2. h = relu([mean1|x] @ [Wl1;Wr1] + b1)   (TF32 tensor cores)
    layer_mma<64, 128, 128, true><<<152, 256, SMEM1>>>(mean1, x, Wl1, Wr1, b1, hbuf);

    // 3. mean-aggregate layer-2 neighbors
    aggregate_kernel<<<(N_NODES * 32 + 255) / 256, 256>>>(hbuf, mean2);

    // 4. out = [mean2|h] @ [Wl2;Wr2] + b2   (TF32 tensor cores)
    layer_mma<128, 64, 40, false><<<152, 256, SMEM2>>>(mean2, hbuf, Wl2, Wr2, b2, out);
}